// round 1
// baseline (speedup 1.0000x reference)
#include <cuda_runtime.h>

// RegionPartitioner: x (8,4,500,500) f32, region_size=64, step=32.
// Padded H=W -> 512 (edge pad == index clamp to 499).
// starts: 0,32,...,448 -> 15 per dim -> 225 regions per batch.
// out shape (8, 225, 4, 64, 64): out[b,r,c,i,j] = x[b,c,min(ri*32+i,499),min(rj*32+j,499)]
// with r = ri*15 + rj.

namespace {
constexpr int B  = 8;
constexpr int C  = 4;
constexpr int H  = 500;
constexpr int W  = 500;
constexpr int RS = 64;
constexpr int ST = 32;
constexpr int NR = 15;          // starts per dim
constexpr int R  = NR * NR;     // 225 regions
constexpr int OUT_ELEMS = B * R * C * RS * RS;   // 29,491,200
constexpr int OUT_VEC4  = OUT_ELEMS / 4;         // 7,372,800
}

__global__ void __launch_bounds__(256)
region_partition_kernel(const float* __restrict__ x, float4* __restrict__ out) {
    int idx = blockIdx.x * blockDim.x + threadIdx.x;
    if (idx >= OUT_VEC4) return;

    // Decompose output float4 index: [b][r][c][i][j4], j4 in 0..15 (4 floats each)
    int j4 = idx & 15;
    int t  = idx >> 4;
    int i  = t & 63;
    t >>= 6;
    int c  = t & 3;
    t >>= 2;                       // t = b*225 + r
    int b  = t / R;
    int r  = t - b * R;
    int ri = r / NR;
    int rj = r - ri * NR;

    int row = ri * ST + i;
    if (row >= H) row = H - 1;     // edge pad (rows)
    int col0 = rj * ST + (j4 << 2);

    const float* __restrict__ src = x + ((b * C + c) * H + row) * (long)W;

    float4 v;
    if (col0 + 3 < W) {
        // 16B-aligned: offset = 500*k + col0, 500%4==0 and col0%4==0
        v = *reinterpret_cast<const float4*>(src + col0);
    } else {
        // edge pad (cols): clamp each lane
        int c0 = col0     < W ? col0     : W - 1;
        int c1 = col0 + 1 < W ? col0 + 1 : W - 1;
        int c2 = col0 + 2 < W ? col0 + 2 : W - 1;
        int c3 = col0 + 3 < W ? col0 + 3 : W - 1;
        v.x = src[c0];
        v.y = src[c1];
        v.z = src[c2];
        v.w = src[c3];
    }
    out[idx] = v;
}

extern "C" void kernel_launch(void* const* d_in, const int* in_sizes, int n_in,
                              void* d_out, int out_size) {
    const float* x = (const float*)d_in[0];
    float4* out = (float4*)d_out;
    const int threads = 256;
    const int blocks = (OUT_VEC4 + threads - 1) / threads;   // 28800
    region_partition_kernel<<<blocks, threads>>>(x, out);
}

// round 2
// speedup vs baseline: 1.2737x; 1.2737x over previous
#include <cuda_runtime.h>

// RegionPartitioner: x (8,4,500,500) f32, region_size=64, step=32.
// Padded H=W -> 512 (edge pad == clamp index to 499).
// 15 starts/dim -> 225 regions/batch. out (8, 225, 4, 64, 64):
// out[b,r,c,i,j] = x[b,c, min(ri*32+i,499), min(rj*32+j,499)], r = ri*15+rj.
//
// Grid: (c=4, r=225, b=8). Each block produces one contiguous 64x64 region
// (4096 floats = 1024 float4). 256 threads x 4 float4 each, loads batched
// for MLP=4.

namespace {
constexpr int C  = 4;
constexpr int H  = 500;
constexpr int W  = 500;
constexpr int ST = 32;
constexpr int NR = 15;
constexpr int R  = NR * NR;   // 225
}

__global__ void __launch_bounds__(256)
region_partition_kernel(const float* __restrict__ x, float4* __restrict__ out) {
    const int c = blockIdx.x;          // 0..3
    const int r = blockIdx.y;          // 0..224
    const int b = blockIdx.z;          // 0..7

    const int ri = r / NR;             // constant-divisor mul-shift
    const int rj = r - ri * NR;

    const int tid = threadIdx.x;
    const int j4  = tid & 15;          // float4 column within region
    const int i0  = tid >> 4;          // starting row within region (0..15)

    const int col0 = rj * ST + (j4 << 2);
    const int row0 = ri * ST + i0;     // rows: row0 + {0,16,32,48}

    const float* __restrict__ plane = x + ((b * C + c) * H) * (long)W;

    // Row indices with edge clamp (only ri==14 can exceed H-1)
    int rw0 = row0;        if (rw0 >= H) rw0 = H - 1;
    int rw1 = row0 + 16;   if (rw1 >= H) rw1 = H - 1;
    int rw2 = row0 + 32;   if (rw2 >= H) rw2 = H - 1;
    int rw3 = row0 + 48;   if (rw3 >= H) rw3 = H - 1;

    const float* s0 = plane + rw0 * W;
    const float* s1 = plane + rw1 * W;
    const float* s2 = plane + rw2 * W;
    const float* s3 = plane + rw3 * W;

    float4 v0, v1, v2, v3;
    if (col0 + 3 < W) {
        // aligned: base offset 500*row + col0, both %4 == 0
        v0 = *reinterpret_cast<const float4*>(s0 + col0);
        v1 = *reinterpret_cast<const float4*>(s1 + col0);
        v2 = *reinterpret_cast<const float4*>(s2 + col0);
        v3 = *reinterpret_cast<const float4*>(s3 + col0);
    } else {
        // column edge clamp (rj==14, j4>=13 only)
        const int c0 = col0     < W ? col0     : W - 1;
        const int c1 = col0 + 1 < W ? col0 + 1 : W - 1;
        const int c2 = col0 + 2 < W ? col0 + 2 : W - 1;
        const int c3 = col0 + 3 < W ? col0 + 3 : W - 1;
        v0.x = s0[c0]; v0.y = s0[c1]; v0.z = s0[c2]; v0.w = s0[c3];
        v1.x = s1[c0]; v1.y = s1[c1]; v1.z = s1[c2]; v1.w = s1[c3];
        v2.x = s2[c0]; v2.y = s2[c1]; v2.z = s2[c2]; v2.w = s2[c3];
        v3.x = s3[c0]; v3.y = s3[c1]; v3.z = s3[c2]; v3.w = s3[c3];
    }

    // Output: region base in float4 units; element f -> (i = f>>4, j4 = f&15)
    float4* __restrict__ dst = out + (((b * R + r) * C + c) << 10) + tid;
    dst[0]   = v0;    // rows i0, i0+16, i0+32, i0+48 <-> f = tid + k*256
    dst[256] = v1;
    dst[512] = v2;
    dst[768] = v3;
}

extern "C" void kernel_launch(void* const* d_in, const int* in_sizes, int n_in,
                              void* d_out, int out_size) {
    const float* x = (const float*)d_in[0];
    float4* out = (float4*)d_out;
    dim3 grid(C, R, 8);
    region_partition_kernel<<<grid, 256>>>(x, out);
}

// round 3
// speedup vs baseline: 1.2857x; 1.0094x over previous
#include <cuda_runtime.h>

// RegionPartitioner: x (8,4,500,500) f32, region=64, step=32, edge pad to 512.
// out (8, 225, 4, 64, 64): out[b,r,c,i,j] = x[b,c,min(ri*32+i,499),min(rj*32+j,499)],
// r = ri*15 + rj, ri/rj in 0..14.
//
// Input-centric: the padded 512x512 plane is tiled into 16x16 quadrant tiles of
// 32x32. Tile (ti,tj) appears in regions ri in {ti-1,ti} (cap [0,14]), same for
// rj, at quadrant (qi,qj) = (ti-ri, tj-rj). One block per (b,c,tile): each input
// element is LOADED EXACTLY ONCE chip-wide, then stored to up to 4 regions.
// Cuts L2 read traffic 4x (118MB -> 32MB); writes stay coalesced float4.

namespace {
constexpr int C  = 4;
constexpr int H  = 500;
constexpr int W  = 500;
constexpr int NR = 15;
constexpr int R  = NR * NR;   // 225
}

__global__ void __launch_bounds__(256)
region_partition_kernel(const float* __restrict__ x, float4* __restrict__ out) {
    const int tile = blockIdx.x;       // 0..255
    const int ti   = tile >> 4;        // 0..15
    const int tj   = tile & 15;        // 0..15
    const int c    = blockIdx.y;
    const int b    = blockIdx.z;

    const int t    = threadIdx.x;
    const int rowl = t >> 3;           // 0..31 row within tile
    const int col4 = t & 7;            // 0..7  float4 col within tile

    // ---- load (exactly once chip-wide), with edge clamp ----
    int row = ti * 32 + rowl;
    if (row >= H) row = H - 1;
    const int col0 = tj * 32 + (col4 << 2);
    const float* __restrict__ src = x + ((b * C + c) * H + row) * (long)W;

    float4 v;
    if (col0 + 3 < W) {
        v = *reinterpret_cast<const float4*>(src + col0);   // 16B aligned
    } else {                                                // tj==15 edge only
        const int c0 = col0     < W ? col0     : W - 1;
        const int c1 = col0 + 1 < W ? col0 + 1 : W - 1;
        const int c2 = col0 + 2 < W ? col0 + 2 : W - 1;
        const int c3 = col0 + 3 < W ? col0 + 3 : W - 1;
        v.x = src[c0]; v.y = src[c1]; v.z = src[c2]; v.w = src[c3];
    }

    // ---- store to up to 4 destination regions (block-uniform branches) ----
    const int breg = b * R;
    #pragma unroll
    for (int di = 0; di < 2; di++) {
        const int ri = ti - 1 + di;
        if (ri < 0 || ri > NR - 1) continue;
        const int qi   = 1 - di;                 // quadrant row in region
        const int orow = (qi << 5) + rowl;       // 0..63
        #pragma unroll
        for (int dj = 0; dj < 2; dj++) {
            const int rj = tj - 1 + dj;
            if (rj < 0 || rj > NR - 1) continue;
            const int qj = 1 - dj;
            // region base in float4 units: ((b*225 + ri*15 + rj)*4 + c) * 1024
            const long base4 = (((long)(breg + ri * NR + rj) * C + c) << 10);
            out[base4 + orow * 16 + (qj << 3) + col4] = v;
        }
    }
}

extern "C" void kernel_launch(void* const* d_in, const int* in_sizes, int n_in,
                              void* d_out, int out_size) {
    const float* x = (const float*)d_in[0];
    float4* out = (float4*)d_out;
    dim3 grid(256, C, 8);              // (tiles, c, b) = 8192 blocks
    region_partition_kernel<<<grid, 256>>>(x, out);
}